// round 1
// baseline (speedup 1.0000x reference)
#include <cuda_runtime.h>

#define NN 8192
#define EE 1024
#define FF 256
#define NW (NN/32)   // 256 words per edge row (transposed bits)
#define EW (EE/32)   // 32 words per node row

// ---- scratch (no allocations allowed; device globals) ----
__device__ float    g_dvis[NN];        // dv^{-1/2}
__device__ float    g_deinv[EE];       // 1/de
__device__ unsigned g_HbT[EE * NW];    // H^T bitpacked: [edge][node-word]
__device__ unsigned g_HbR[NN * EW];    // H bitpacked:   [node][edge-word]
__device__ float    g_M [EE * FF];     // edge features
__device__ float    g_Xn[NN * FF];     // node features pre-linear

// ============================================================
// Pack H into column-major (edge-major) bits + compute dv^{-1/2}
// block = 256 threads handles 32 rows x all 1024 cols
// lane = row-within-tile, warp strides over columns
// ============================================================
__global__ void __launch_bounds__(256) pack_T(const float* __restrict__ H) {
    const int r0   = blockIdx.x * 32;
    const int lane = threadIdx.x & 31;
    const int wid  = threadIdx.x >> 5;
    const int row  = r0 + lane;
    const float* hrow = H + (long)row * EE;

    __shared__ float sdv[32];
    if (threadIdx.x < 32) sdv[threadIdx.x] = 0.f;
    __syncthreads();

    float dvp = 0.f;
    const int wordIdx = r0 >> 5;
    for (int c = wid; c < EE; c += 8) {
        float v = hrow[c];
        dvp += v;
        unsigned m = __ballot_sync(0xffffffffu, v != 0.f);
        if (lane == 0) g_HbT[c * NW + wordIdx] = m;
    }
    atomicAdd(&sdv[lane], dvp);      // integer-valued floats: exact, order-independent
    __syncthreads();
    if (threadIdx.x < 32)
        g_dvis[r0 + threadIdx.x] = rsqrtf(sdv[threadIdx.x]);
}

// ============================================================
// Pack H into row-major (node-major) bits. One warp per row.
// ============================================================
__global__ void __launch_bounds__(256) pack_R(const float* __restrict__ H) {
    const int row  = blockIdx.x * 8 + (threadIdx.x >> 5);
    const int lane = threadIdx.x & 31;
    const float* hrow = H + (long)row * EE;
    #pragma unroll
    for (int w = 0; w < EW; ++w) {
        float v = hrow[w * 32 + lane];
        unsigned m = __ballot_sync(0xffffffffu, v != 0.f);
        if (lane == 0) g_HbR[row * EW + w] = m;
    }
}

// ============================================================
// Edge degrees from packed bits -> 1/de
// ============================================================
__global__ void __launch_bounds__(256) calc_deinv() {
    const int e = blockIdx.x * 256 + threadIdx.x;
    const unsigned* p = &g_HbT[e * NW];
    int s = 0;
    #pragma unroll 8
    for (int w = 0; w < NW; ++w) s += __popc(p[w]);
    g_deinv[e] = 1.f / (float)s;
}

// ============================================================
// Pass A: M[e] = deinv[e] * sum_{i in e} dvis[i] * X[i]
// one CTA per edge, thread t owns feature column t.
// Node indices extracted once (deterministic order) into smem.
// ============================================================
#define MAX_DE 1024
__global__ void __launch_bounds__(256) edge_gather(const float* __restrict__ X) {
    const int e = blockIdx.x;
    const int t = threadIdx.x;
    const int lane = t & 31, wid = t >> 5;

    __shared__ unsigned short sidx[MAX_DE];
    __shared__ float          sdvv[MAX_DE];
    __shared__ int wtot[8];
    __shared__ int warpOff[9];

    unsigned m = g_HbT[e * NW + t];
    int cnt = __popc(m);

    // inclusive scan within warp
    int scan = cnt;
    #pragma unroll
    for (int o = 1; o < 32; o <<= 1) {
        int v = __shfl_up_sync(0xffffffffu, scan, o);
        if (lane >= o) scan += v;
    }
    if (lane == 31) wtot[wid] = scan;
    __syncthreads();
    if (t == 0) {
        int s = 0;
        #pragma unroll
        for (int w = 0; w < 8; ++w) { warpOff[w] = s; s += wtot[w]; }
        warpOff[8] = s;
    }
    __syncthreads();

    int off = warpOff[wid] + (scan - cnt);   // exclusive offset
    const int base = t * 32;
    while (m) {
        int b = __ffs(m) - 1;
        m &= m - 1;
        int node = base + b;
        sidx[off] = (unsigned short)node;
        sdvv[off] = g_dvis[node];
        ++off;
    }
    __syncthreads();

    const int total = warpOff[8];
    float acc = 0.f;
    int j = 0;
    for (; j + 4 <= total; j += 4) {
        int n0 = sidx[j+0], n1 = sidx[j+1], n2 = sidx[j+2], n3 = sidx[j+3];
        float x0 = X[n0 * FF + t];
        float x1 = X[n1 * FF + t];
        float x2 = X[n2 * FF + t];
        float x3 = X[n3 * FF + t];
        acc = fmaf(x0, sdvv[j+0], acc);
        acc = fmaf(x1, sdvv[j+1], acc);
        acc = fmaf(x2, sdvv[j+2], acc);
        acc = fmaf(x3, sdvv[j+3], acc);
    }
    for (; j < total; ++j)
        acc = fmaf(X[sidx[j] * FF + t], sdvv[j], acc);

    g_M[e * FF + t] = acc * g_deinv[e];
}

// ============================================================
// Pass B: Xn[i] = dvis[i] * sum_{e ni i} M[e]
// one CTA per node, thread t owns feature column t.
// ============================================================
#define MAX_DV 256
__global__ void __launch_bounds__(256) node_gather() {
    const int i = blockIdx.x;
    const int t = threadIdx.x;

    __shared__ unsigned short sidx[MAX_DV];
    __shared__ int stotal;

    if (t < 32) {
        unsigned m = g_HbR[i * EW + t];
        int cnt = __popc(m);
        int scan = cnt;
        #pragma unroll
        for (int o = 1; o < 32; o <<= 1) {
            int v = __shfl_up_sync(0xffffffffu, scan, o);
            if (t >= o) scan += v;
        }
        int off = scan - cnt;
        const int base = t * 32;
        while (m) {
            int b = __ffs(m) - 1;
            m &= m - 1;
            sidx[off++] = (unsigned short)(base + b);
        }
        if (t == 31) stotal = scan;
    }
    __syncthreads();

    const int total = stotal;
    float acc = 0.f;
    int j = 0;
    for (; j + 4 <= total; j += 4) {
        float m0 = g_M[sidx[j+0] * FF + t];
        float m1 = g_M[sidx[j+1] * FF + t];
        float m2 = g_M[sidx[j+2] * FF + t];
        float m3 = g_M[sidx[j+3] * FF + t];
        acc += m0; acc += m1; acc += m2; acc += m3;
    }
    for (; j < total; ++j)
        acc += g_M[sidx[j] * FF + t];

    g_Xn[i * FF + t] = acc * g_dvis[i];
}

// ============================================================
// out = Xn @ W^T + b      (NT GEMM: both K-major)
// BM=128, BN=64, BK=32, 256 threads, 8x4 register tile
// ============================================================
__global__ void __launch_bounds__(256) gemm_out(const float* __restrict__ Wm,
                                                const float* __restrict__ bias,
                                                float* __restrict__ out) {
    __shared__ float As[32][128];   // As[k][i]
    __shared__ float Bs[32][64];    // Bs[k][o]

    const int tid = threadIdx.x;
    const int ty = tid >> 4;   // 0..15 -> 8 rows each
    const int tx = tid & 15;   // 0..15 -> 4 cols each
    const int i0 = blockIdx.y * 128;
    const int o0 = blockIdx.x * 64;

    float acc[8][4];
    #pragma unroll
    for (int r = 0; r < 8; ++r)
        #pragma unroll
        for (int c = 0; c < 4; ++c) acc[r][c] = 0.f;

    for (int kc = 0; kc < FF; kc += 32) {
        // A tile: 128x32 floats = 1024 float4, 4/thread
        #pragma unroll
        for (int l = 0; l < 4; ++l) {
            int linear = tid + 256 * l;
            int i  = linear >> 3;
            int kq = (linear & 7) << 2;
            float4 v = *(const float4*)&g_Xn[(i0 + i) * FF + kc + kq];
            As[kq + 0][i] = v.x; As[kq + 1][i] = v.y;
            As[kq + 2][i] = v.z; As[kq + 3][i] = v.w;
        }
        // B tile: 64x32 floats = 512 float4, 2/thread
        #pragma unroll
        for (int l = 0; l < 2; ++l) {
            int linear = tid + 256 * l;
            int o  = linear >> 3;
            int kq = (linear & 7) << 2;
            float4 v = *(const float4*)&Wm[(o0 + o) * FF + kc + kq];
            Bs[kq + 0][o] = v.x; Bs[kq + 1][o] = v.y;
            Bs[kq + 2][o] = v.z; Bs[kq + 3][o] = v.w;
        }
        __syncthreads();
        #pragma unroll
        for (int kk = 0; kk < 32; ++kk) {
            float4 b4 = *(const float4*)&Bs[kk][tx * 4];
            float4 a0 = *(const float4*)&As[kk][ty * 8];
            float4 a1 = *(const float4*)&As[kk][ty * 8 + 4];
            float a[8] = {a0.x, a0.y, a0.z, a0.w, a1.x, a1.y, a1.z, a1.w};
            float bb[4] = {b4.x, b4.y, b4.z, b4.w};
            #pragma unroll
            for (int r = 0; r < 8; ++r)
                #pragma unroll
                for (int c = 0; c < 4; ++c)
                    acc[r][c] = fmaf(a[r], bb[c], acc[r][c]);
        }
        __syncthreads();
    }

    float4 bv = *(const float4*)&bias[o0 + tx * 4];
    #pragma unroll
    for (int r = 0; r < 8; ++r) {
        int i = i0 + ty * 8 + r;
        float4 o4;
        o4.x = acc[r][0] + bv.x;
        o4.y = acc[r][1] + bv.y;
        o4.z = acc[r][2] + bv.z;
        o4.w = acc[r][3] + bv.w;
        *(float4*)&out[i * FF + o0 + tx * 4] = o4;
    }
}

// ============================================================
extern "C" void kernel_launch(void* const* d_in, const int* in_sizes, int n_in,
                              void* d_out, int out_size) {
    const float* X    = (const float*)d_in[0];   // [8192,256]
    const float* H    = (const float*)d_in[1];   // [8192,1024]
    const float* Wm   = (const float*)d_in[2];   // [256,256]
    const float* bias = (const float*)d_in[3];   // [256]
    float* out = (float*)d_out;

    pack_T     <<<NN / 32, 256>>>(H);
    pack_R     <<<NN / 8,  256>>>(H);
    calc_deinv <<<EE / 256, 256>>>();
    edge_gather<<<EE, 256>>>(X);
    node_gather<<<NN, 256>>>();
    dim3 g(FF / 64, NN / 128);
    gemm_out   <<<g, 256>>>(Wm, bias, out);
}

// round 2
// speedup vs baseline: 1.4567x; 1.4567x over previous
#include <cuda_runtime.h>

#define NN 8192
#define EE 1024
#define FF 256
#define NW (NN/32)   // 256 words per edge row (transposed bits)
#define EW (EE/32)   // 32 words per node row

// ---- scratch (no allocations allowed; device globals) ----
__device__ float    g_dvis[NN];                     // dv^{-1/2}
__device__ float    g_deinv[EE];                    // 1/de
__device__ unsigned g_HbT[EE * NW];                 // H^T bitpacked: [edge][node-word]
__device__ unsigned g_HbR[NN * EW];                 // H bitpacked:   [node][edge-word]
__device__ __align__(16) float g_M [EE * FF];       // edge features
__device__ __align__(16) float g_Xn[NN * FF];       // node features pre-linear

// ============================================================
// One-pass pack: coalesced read of H, produces HbR, HbT (via
// in-warp bit transpose) and dv^{-1/2}. CTA = 32 rows x 1024 cols.
// ============================================================
__global__ void __launch_bounds__(256) pack_all(const float* __restrict__ H) {
    const int r0 = blockIdx.x * 32;
    const int w  = threadIdx.x >> 5;
    const int l  = threadIdx.x & 31;

    __shared__ unsigned smask[32][32];   // [col-chunk][row] row-bitmasks

    int cnt[4] = {0, 0, 0, 0};
    for (int ch = 0; ch < 32; ++ch) {
        const int c0 = ch * 32;
        #pragma unroll
        for (int k = 0; k < 4; ++k) {
            const int row = w + 8 * k;
            float v = H[(long)(r0 + row) * EE + c0 + l];   // 128B coalesced
            unsigned m = __ballot_sync(0xffffffffu, v != 0.f);
            cnt[k] += __popc(m);
            if (l == 0) {
                smask[ch][row] = m;
                g_HbR[(r0 + row) * EW + ch] = m;
            }
        }
    }
    if (l == 0) {
        #pragma unroll
        for (int k = 0; k < 4; ++k)
            g_dvis[r0 + w + 8 * k] = rsqrtf((float)cnt[k]);
    }
    __syncthreads();

    // transpose 32x32 bit tiles: warp w handles chunks w, w+8, w+16, w+24
    const int wordIdx = blockIdx.x;                  // = r0 >> 5
    #pragma unroll
    for (int q = 0; q < 4; ++q) {
        const int cc = w + 8 * q;
        const unsigned rm = smask[cc][l];            // lane l = row l's mask
        #pragma unroll
        for (int c = 0; c < 32; ++c) {
            unsigned colm = __ballot_sync(0xffffffffu, (rm >> c) & 1u);
            if (l == 0) g_HbT[(cc * 32 + c) * NW + wordIdx] = colm;
        }
    }
}

// ============================================================
// Edge degrees from packed bits -> 1/de
// ============================================================
__global__ void __launch_bounds__(256) calc_deinv() {
    const int e = blockIdx.x * 256 + threadIdx.x;
    const unsigned* p = &g_HbT[e * NW];
    int s = 0;
    #pragma unroll 8
    for (int w = 0; w < NW; ++w) s += __popc(p[w]);
    g_deinv[e] = 1.f / (float)s;
}

// ============================================================
// Pass A: M[e] = deinv[e] * sum_{i in e} dvis[i] * X[i]
// one CTA per edge. 4 row-groups x 64 threads, float4 per thread.
// ============================================================
#define MAX_DE 1024
__global__ void __launch_bounds__(256) edge_gather(const float* __restrict__ X) {
    const int e = blockIdx.x;
    const int t = threadIdx.x;
    const int lane = t & 31, wid = t >> 5;
    const int f = t & 63;          // float4 column
    const int g = t >> 6;          // row group 0..3

    __shared__ unsigned short sidx[MAX_DE];
    __shared__ float          sdvv[MAX_DE];
    __shared__ int wtot[8];
    __shared__ int warpOff[9];
    __shared__ float4 red[256];

    // ---- extract node indices (deterministic order) ----
    unsigned m = g_HbT[e * NW + t];
    int cnt = __popc(m);
    int scan = cnt;
    #pragma unroll
    for (int o = 1; o < 32; o <<= 1) {
        int v = __shfl_up_sync(0xffffffffu, scan, o);
        if (lane >= o) scan += v;
    }
    if (lane == 31) wtot[wid] = scan;
    __syncthreads();
    if (t == 0) {
        int s = 0;
        #pragma unroll
        for (int w = 0; w < 8; ++w) { warpOff[w] = s; s += wtot[w]; }
        warpOff[8] = s;
    }
    __syncthreads();

    int off = warpOff[wid] + (scan - cnt);
    const int base = t * 32;
    while (m) {
        int b = __ffs(m) - 1;
        m &= m - 1;
        int node = base + b;
        sidx[off] = (unsigned short)node;
        sdvv[off] = g_dvis[node];
        ++off;
    }
    __syncthreads();

    // ---- gather: group g takes rows j = g, g+4, ... ----
    const int total = warpOff[8];
    const float4* X4 = (const float4*)X;
    float4 acc = make_float4(0.f, 0.f, 0.f, 0.f);

    int j = g;
    for (; j + 12 < total; j += 16) {
        int   n0 = sidx[j],      n1 = sidx[j + 4],  n2 = sidx[j + 8],  n3 = sidx[j + 12];
        float s0 = sdvv[j],      s1 = sdvv[j + 4],  s2 = sdvv[j + 8],  s3 = sdvv[j + 12];
        float4 x0 = X4[n0 * 64 + f];
        float4 x1 = X4[n1 * 64 + f];
        float4 x2 = X4[n2 * 64 + f];
        float4 x3 = X4[n3 * 64 + f];
        acc.x = fmaf(x0.x, s0, acc.x); acc.y = fmaf(x0.y, s0, acc.y);
        acc.z = fmaf(x0.z, s0, acc.z); acc.w = fmaf(x0.w, s0, acc.w);
        acc.x = fmaf(x1.x, s1, acc.x); acc.y = fmaf(x1.y, s1, acc.y);
        acc.z = fmaf(x1.z, s1, acc.z); acc.w = fmaf(x1.w, s1, acc.w);
        acc.x = fmaf(x2.x, s2, acc.x); acc.y = fmaf(x2.y, s2, acc.y);
        acc.z = fmaf(x2.z, s2, acc.z); acc.w = fmaf(x2.w, s2, acc.w);
        acc.x = fmaf(x3.x, s3, acc.x); acc.y = fmaf(x3.y, s3, acc.y);
        acc.z = fmaf(x3.z, s3, acc.z); acc.w = fmaf(x3.w, s3, acc.w);
    }
    for (; j < total; j += 4) {
        int n = sidx[j]; float s = sdvv[j];
        float4 x = X4[n * 64 + f];
        acc.x = fmaf(x.x, s, acc.x); acc.y = fmaf(x.y, s, acc.y);
        acc.z = fmaf(x.z, s, acc.z); acc.w = fmaf(x.w, s, acc.w);
    }

    red[t] = acc;
    __syncthreads();
    if (g == 0) {
        float4 a = red[f], b = red[f + 64], c = red[f + 128], d = red[f + 192];
        float di = g_deinv[e];
        float4 o;
        o.x = (a.x + b.x + c.x + d.x) * di;
        o.y = (a.y + b.y + c.y + d.y) * di;
        o.z = (a.z + b.z + c.z + d.z) * di;
        o.w = (a.w + b.w + c.w + d.w) * di;
        *(float4*)&g_M[e * FF + f * 4] = o;
    }
}

// ============================================================
// Pass B: Xn[i] = dvis[i] * sum_{e ni i} M[e]
// one CTA per node. 4 row-groups x 64 threads, float4 per thread.
// ============================================================
#define MAX_DV 256
__global__ void __launch_bounds__(256) node_gather() {
    const int i = blockIdx.x;
    const int t = threadIdx.x;
    const int f = t & 63;
    const int g = t >> 6;

    __shared__ unsigned short sidx[MAX_DV];
    __shared__ int stotal;
    __shared__ float4 red[256];

    if (t < 32) {
        unsigned m = g_HbR[i * EW + t];
        int cnt = __popc(m);
        int scan = cnt;
        #pragma unroll
        for (int o = 1; o < 32; o <<= 1) {
            int v = __shfl_up_sync(0xffffffffu, scan, o);
            if (t >= o) scan += v;
        }
        int off = scan - cnt;
        const int base = t * 32;
        while (m) {
            int b = __ffs(m) - 1;
            m &= m - 1;
            sidx[off++] = (unsigned short)(base + b);
        }
        if (t == 31) stotal = scan;
    }
    __syncthreads();

    const int total = stotal;
    const float4* M4 = (const float4*)g_M;
    float4 acc = make_float4(0.f, 0.f, 0.f, 0.f);

    int j = g;
    for (; j + 12 < total; j += 16) {
        int e0 = sidx[j], e1 = sidx[j + 4], e2 = sidx[j + 8], e3 = sidx[j + 12];
        float4 x0 = M4[e0 * 64 + f];
        float4 x1 = M4[e1 * 64 + f];
        float4 x2 = M4[e2 * 64 + f];
        float4 x3 = M4[e3 * 64 + f];
        acc.x += x0.x + x1.x + x2.x + x3.x;
        acc.y += x0.y + x1.y + x2.y + x3.y;
        acc.z += x0.z + x1.z + x2.z + x3.z;
        acc.w += x0.w + x1.w + x2.w + x3.w;
    }
    for (; j < total; j += 4) {
        float4 x = M4[sidx[j] * 64 + f];
        acc.x += x.x; acc.y += x.y; acc.z += x.z; acc.w += x.w;
    }

    red[t] = acc;
    __syncthreads();
    if (g == 0) {
        float4 a = red[f], b = red[f + 64], c = red[f + 128], d = red[f + 192];
        float dv = g_dvis[i];
        float4 o;
        o.x = (a.x + b.x + c.x + d.x) * dv;
        o.y = (a.y + b.y + c.y + d.y) * dv;
        o.z = (a.z + b.z + c.z + d.z) * dv;
        o.w = (a.w + b.w + c.w + d.w) * dv;
        *(float4*)&g_Xn[i * FF + f * 4] = o;
    }
}

// ============================================================
// out = Xn @ W^T + b      (NT GEMM: both K-major)
// BM=128, BN=64, BK=32, 256 threads, 8x4 register tile
// ============================================================
__global__ void __launch_bounds__(256) gemm_out(const float* __restrict__ Wm,
                                                const float* __restrict__ bias,
                                                float* __restrict__ out) {
    __shared__ float As[32][128];   // As[k][i]
    __shared__ float Bs[32][64];    // Bs[k][o]

    const int tid = threadIdx.x;
    const int ty = tid >> 4;   // 0..15 -> 8 rows each
    const int tx = tid & 15;   // 0..15 -> 4 cols each
    const int i0 = blockIdx.y * 128;
    const int o0 = blockIdx.x * 64;

    float acc[8][4];
    #pragma unroll
    for (int r = 0; r < 8; ++r)
        #pragma unroll
        for (int c = 0; c < 4; ++c) acc[r][c] = 0.f;

    for (int kc = 0; kc < FF; kc += 32) {
        #pragma unroll
        for (int l = 0; l < 4; ++l) {
            int linear = tid + 256 * l;
            int i  = linear >> 3;
            int kq = (linear & 7) << 2;
            float4 v = *(const float4*)&g_Xn[(i0 + i) * FF + kc + kq];
            As[kq + 0][i] = v.x; As[kq + 1][i] = v.y;
            As[kq + 2][i] = v.z; As[kq + 3][i] = v.w;
        }
        #pragma unroll
        for (int l = 0; l < 2; ++l) {
            int linear = tid + 256 * l;
            int o  = linear >> 3;
            int kq = (linear & 7) << 2;
            float4 v = *(const float4*)&Wm[(o0 + o) * FF + kc + kq];
            Bs[kq + 0][o] = v.x; Bs[kq + 1][o] = v.y;
            Bs[kq + 2][o] = v.z; Bs[kq + 3][o] = v.w;
        }
        __syncthreads();
        #pragma unroll
        for (int kk = 0; kk < 32; ++kk) {
            float4 b4 = *(const float4*)&Bs[kk][tx * 4];
            float4 a0 = *(const float4*)&As[kk][ty * 8];
            float4 a1 = *(const float4*)&As[kk][ty * 8 + 4];
            float a[8] = {a0.x, a0.y, a0.z, a0.w, a1.x, a1.y, a1.z, a1.w};
            float bb[4] = {b4.x, b4.y, b4.z, b4.w};
            #pragma unroll
            for (int r = 0; r < 8; ++r)
                #pragma unroll
                for (int c = 0; c < 4; ++c)
                    acc[r][c] = fmaf(a[r], bb[c], acc[r][c]);
        }
        __syncthreads();
    }

    float4 bv = *(const float4*)&bias[o0 + tx * 4];
    #pragma unroll
    for (int r = 0; r < 8; ++r) {
        int i = i0 + ty * 8 + r;
        float4 o4;
        o4.x = acc[r][0] + bv.x;
        o4.y = acc[r][1] + bv.y;
        o4.z = acc[r][2] + bv.z;
        o4.w = acc[r][3] + bv.w;
        *(float4*)&out[i * FF + o0 + tx * 4] = o4;
    }
}

// ============================================================
extern "C" void kernel_launch(void* const* d_in, const int* in_sizes, int n_in,
                              void* d_out, int out_size) {
    const float* X    = (const float*)d_in[0];   // [8192,256]
    const float* H    = (const float*)d_in[1];   // [8192,1024]
    const float* Wm   = (const float*)d_in[2];   // [256,256]
    const float* bias = (const float*)d_in[3];   // [256]
    float* out = (float*)d_out;

    pack_all   <<<NN / 32, 256>>>(H);
    calc_deinv <<<EE / 256, 256>>>();
    edge_gather<<<EE, 256>>>(X);
    node_gather<<<NN, 256>>>();
    dim3 g(FF / 64, NN / 128);
    gemm_out   <<<g, 256>>>(Wm, bias, out);
}

// round 4
// speedup vs baseline: 2.3017x; 1.5801x over previous
#include <cuda_runtime.h>

#define NN 8192
#define EE 1024
#define FF 256
#define NW (NN/32)   // 256 words per edge row (transposed bits)
#define EW (EE/32)   // 32 words per node row

// ---- scratch (no allocations allowed; device globals) ----
__device__ float    g_dvis[NN];                     // dv^{-1/2}
__device__ unsigned g_HbT[EE * NW];                 // H^T bitpacked: [edge][node-word]
__device__ unsigned g_HbR[NN * EW];                 // H bitpacked:   [node][edge-word]
__device__ __align__(16) float g_M [EE * FF];       // edge features (De^-1 H^T Dv^-1/2 X)
__device__ __align__(16) float g_MW[EE * FF];       // M @ W^T

// ============================================================
// One-pass pack: coalesced read of H, produces HbR, HbT (via
// in-warp bit transpose) and dv^{-1/2}. CTA = 32 rows x 1024 cols.
// ============================================================
__global__ void __launch_bounds__(256) pack_all(const float* __restrict__ H) {
    const int r0 = blockIdx.x * 32;
    const int w  = threadIdx.x >> 5;
    const int l  = threadIdx.x & 31;

    __shared__ unsigned smask[32][32];   // [col-chunk][row] row-bitmasks

    int cnt[4] = {0, 0, 0, 0};
    for (int ch = 0; ch < 32; ++ch) {
        const int c0 = ch * 32;
        #pragma unroll
        for (int k = 0; k < 4; ++k) {
            const int row = w + 8 * k;
            float v = H[(long)(r0 + row) * EE + c0 + l];   // 128B coalesced
            unsigned m = __ballot_sync(0xffffffffu, v != 0.f);
            cnt[k] += __popc(m);
            if (l == 0) {
                smask[ch][row] = m;
                g_HbR[(r0 + row) * EW + ch] = m;
            }
        }
    }
    if (l == 0) {
        #pragma unroll
        for (int k = 0; k < 4; ++k)
            g_dvis[r0 + w + 8 * k] = rsqrtf((float)cnt[k]);
    }
    __syncthreads();

    // transpose 32x32 bit tiles: warp w handles chunks w, w+8, w+16, w+24
    const int wordIdx = blockIdx.x;                  // = r0 >> 5
    #pragma unroll
    for (int q = 0; q < 4; ++q) {
        const int cc = w + 8 * q;
        const unsigned rm = smask[cc][l];            // lane l = row l's mask
        #pragma unroll
        for (int c = 0; c < 32; ++c) {
            unsigned colm = __ballot_sync(0xffffffffu, (rm >> c) & 1u);
            if (l == 0) g_HbT[(cc * 32 + c) * NW + wordIdx] = colm;
        }
    }
}

// ============================================================
// Pass A: M[e] = (1/de) * sum_{i in e} dvis[i] * X[i]
// one CTA per edge. 4 row-groups x 64 threads, float4 per thread.
// de computed in-kernel from the extraction scan (no extra pass).
// ============================================================
#define MAX_DE 1024
__global__ void __launch_bounds__(256) edge_gather(const float* __restrict__ X) {
    const int e = blockIdx.x;
    const int t = threadIdx.x;
    const int lane = t & 31, wid = t >> 5;
    const int f = t & 63;          // float4 column
    const int g = t >> 6;          // row group 0..3

    __shared__ unsigned short sidx[MAX_DE];
    __shared__ float          sdvv[MAX_DE];
    __shared__ int wtot[8];
    __shared__ int warpOff[9];
    __shared__ float4 red[256];

    // ---- extract node indices (deterministic order) ----
    unsigned m = g_HbT[e * NW + t];
    int cnt = __popc(m);
    int scan = cnt;
    #pragma unroll
    for (int o = 1; o < 32; o <<= 1) {
        int v = __shfl_up_sync(0xffffffffu, scan, o);
        if (lane >= o) scan += v;
    }
    if (lane == 31) wtot[wid] = scan;
    __syncthreads();
    if (t == 0) {
        int s = 0;
        #pragma unroll
        for (int w = 0; w < 8; ++w) { warpOff[w] = s; s += wtot[w]; }
        warpOff[8] = s;
    }
    __syncthreads();

    int off = warpOff[wid] + (scan - cnt);
    const int base = t * 32;
    while (m) {
        int b = __ffs(m) - 1;
        m &= m - 1;
        int node = base + b;
        sidx[off] = (unsigned short)node;
        sdvv[off] = g_dvis[node];
        ++off;
    }
    __syncthreads();

    // ---- gather: group g takes rows j = g, g+4, ... 8 loads in flight ----
    const int total = warpOff[8];
    const float4* X4 = (const float4*)X;
    float4 acc = make_float4(0.f, 0.f, 0.f, 0.f);

    int j = g;
    for (; j + 28 < total; j += 32) {
        int   n0 = sidx[j],      n1 = sidx[j + 4],  n2 = sidx[j + 8],  n3 = sidx[j + 12];
        int   n4 = sidx[j + 16], n5 = sidx[j + 20], n6 = sidx[j + 24], n7 = sidx[j + 28];
        float s0 = sdvv[j],      s1 = sdvv[j + 4],  s2 = sdvv[j + 8],  s3 = sdvv[j + 12];
        float s4 = sdvv[j + 16], s5 = sdvv[j + 20], s6 = sdvv[j + 24], s7 = sdvv[j + 28];
        float4 x0 = X4[n0 * 64 + f];
        float4 x1 = X4[n1 * 64 + f];
        float4 x2 = X4[n2 * 64 + f];
        float4 x3 = X4[n3 * 64 + f];
        float4 x4 = X4[n4 * 64 + f];
        float4 x5 = X4[n5 * 64 + f];
        float4 x6 = X4[n6 * 64 + f];
        float4 x7 = X4[n7 * 64 + f];
        acc.x = fmaf(x0.x, s0, acc.x); acc.y = fmaf(x0.y, s0, acc.y);
        acc.z = fmaf(x0.z, s0, acc.z); acc.w = fmaf(x0.w, s0, acc.w);
        acc.x = fmaf(x1.x, s1, acc.x); acc.y = fmaf(x1.y, s1, acc.y);
        acc.z = fmaf(x1.z, s1, acc.z); acc.w = fmaf(x1.w, s1, acc.w);
        acc.x = fmaf(x2.x, s2, acc.x); acc.y = fmaf(x2.y, s2, acc.y);
        acc.z = fmaf(x2.z, s2, acc.z); acc.w = fmaf(x2.w, s2, acc.w);
        acc.x = fmaf(x3.x, s3, acc.x); acc.y = fmaf(x3.y, s3, acc.y);
        acc.z = fmaf(x3.z, s3, acc.z); acc.w = fmaf(x3.w, s3, acc.w);
        acc.x = fmaf(x4.x, s4, acc.x); acc.y = fmaf(x4.y, s4, acc.y);
        acc.z = fmaf(x4.z, s4, acc.z); acc.w = fmaf(x4.w, s4, acc.w);
        acc.x = fmaf(x5.x, s5, acc.x); acc.y = fmaf(x5.y, s5, acc.y);
        acc.z = fmaf(x5.z, s5, acc.z); acc.w = fmaf(x5.w, s5, acc.w);
        acc.x = fmaf(x6.x, s6, acc.x); acc.y = fmaf(x6.y, s6, acc.y);
        acc.z = fmaf(x6.z, s6, acc.z); acc.w = fmaf(x6.w, s6, acc.w);
        acc.x = fmaf(x7.x, s7, acc.x); acc.y = fmaf(x7.y, s7, acc.y);
        acc.z = fmaf(x7.z, s7, acc.z); acc.w = fmaf(x7.w, s7, acc.w);
    }
    for (; j < total; j += 4) {
        int n = sidx[j]; float s = sdvv[j];
        float4 x = X4[n * 64 + f];
        acc.x = fmaf(x.x, s, acc.x); acc.y = fmaf(x.y, s, acc.y);
        acc.z = fmaf(x.z, s, acc.z); acc.w = fmaf(x.w, s, acc.w);
    }

    red[t] = acc;
    __syncthreads();
    if (g == 0) {
        float4 a = red[f], b = red[f + 64], c = red[f + 128], d = red[f + 192];
        float di = 1.f / (float)total;
        float4 o;
        o.x = (a.x + b.x + c.x + d.x) * di;
        o.y = (a.y + b.y + c.y + d.y) * di;
        o.z = (a.z + b.z + c.z + d.z) * di;
        o.w = (a.w + b.w + c.w + d.w) * di;
        *(float4*)&g_M[e * FF + f * 4] = o;
    }
}

// ============================================================
// g_MW = g_M @ W^T   ([1024,256] @ [256,256], both K-major)
// BM=128, BN=64, BK=32, 256 threads, 8x4 register tile.
// NOTE: g_MW referenced INSIDE the kernel (device symbol — cannot
// be passed as a kernel argument from host code).
// ============================================================
__global__ void __launch_bounds__(256) gemm_mw(const float* __restrict__ Wm) {
    __shared__ float As[32][128];   // As[k][e]
    __shared__ float Bs[32][64];    // Bs[k][o]

    const int tid = threadIdx.x;
    const int ty = tid >> 4;   // 0..15 -> 8 rows each
    const int tx = tid & 15;   // 0..15 -> 4 cols each
    const int i0 = blockIdx.y * 128;
    const int o0 = blockIdx.x * 64;

    float acc[8][4];
    #pragma unroll
    for (int r = 0; r < 8; ++r)
        #pragma unroll
        for (int c = 0; c < 4; ++c) acc[r][c] = 0.f;

    for (int kc = 0; kc < FF; kc += 32) {
        #pragma unroll
        for (int l = 0; l < 4; ++l) {
            int linear = tid + 256 * l;
            int i  = linear >> 3;
            int kq = (linear & 7) << 2;
            float4 v = *(const float4*)&g_M[(i0 + i) * FF + kc + kq];
            As[kq + 0][i] = v.x; As[kq + 1][i] = v.y;
            As[kq + 2][i] = v.z; As[kq + 3][i] = v.w;
        }
        #pragma unroll
        for (int l = 0; l < 2; ++l) {
            int linear = tid + 256 * l;
            int o  = linear >> 3;
            int kq = (linear & 7) << 2;
            float4 v = *(const float4*)&Wm[(o0 + o) * FF + kc + kq];
            Bs[kq + 0][o] = v.x; Bs[kq + 1][o] = v.y;
            Bs[kq + 2][o] = v.z; Bs[kq + 3][o] = v.w;
        }
        __syncthreads();
        #pragma unroll
        for (int kk = 0; kk < 32; ++kk) {
            float4 b4 = *(const float4*)&Bs[kk][tx * 4];
            float4 a0 = *(const float4*)&As[kk][ty * 8];
            float4 a1 = *(const float4*)&As[kk][ty * 8 + 4];
            float a[8] = {a0.x, a0.y, a0.z, a0.w, a1.x, a1.y, a1.z, a1.w};
            float bb[4] = {b4.x, b4.y, b4.z, b4.w};
            #pragma unroll
            for (int r = 0; r < 8; ++r)
                #pragma unroll
                for (int c = 0; c < 4; ++c)
                    acc[r][c] = fmaf(a[r], bb[c], acc[r][c]);
        }
        __syncthreads();
    }

    #pragma unroll
    for (int r = 0; r < 8; ++r) {
        int i = i0 + ty * 8 + r;
        float4 o4;
        o4.x = acc[r][0]; o4.y = acc[r][1];
        o4.z = acc[r][2]; o4.w = acc[r][3];
        *(float4*)&g_MW[i * FF + o0 + tx * 4] = o4;
    }
}

// ============================================================
// Pass B (fused epilogue): out[i] = dvis[i] * sum_{e ni i} MW[e] + b
// one CTA per node. 4 row-groups x 64 threads, float4 per thread.
// ============================================================
#define MAX_DV 256
__global__ void __launch_bounds__(256) node_gather(const float* __restrict__ bias,
                                                   float* __restrict__ out) {
    const int i = blockIdx.x;
    const int t = threadIdx.x;
    const int f = t & 63;
    const int g = t >> 6;

    __shared__ unsigned short sidx[MAX_DV];
    __shared__ int stotal;
    __shared__ float4 red[256];

    if (t < 32) {
        unsigned m = g_HbR[i * EW + t];
        int cnt = __popc(m);
        int scan = cnt;
        #pragma unroll
        for (int o = 1; o < 32; o <<= 1) {
            int v = __shfl_up_sync(0xffffffffu, scan, o);
            if (t >= o) scan += v;
        }
        int off = scan - cnt;
        const int base = t * 32;
        while (m) {
            int b = __ffs(m) - 1;
            m &= m - 1;
            sidx[off++] = (unsigned short)(base + b);
        }
        if (t == 31) stotal = scan;
    }
    __syncthreads();

    const int total = stotal;
    const float4* M4 = (const float4*)g_MW;
    float4 acc = make_float4(0.f, 0.f, 0.f, 0.f);

    int j = g;
    for (; j + 12 < total; j += 16) {
        int e0 = sidx[j], e1 = sidx[j + 4], e2 = sidx[j + 8], e3 = sidx[j + 12];
        float4 x0 = M4[e0 * 64 + f];
        float4 x1 = M4[e1 * 64 + f];
        float4 x2 = M4[e2 * 64 + f];
        float4 x3 = M4[e3 * 64 + f];
        acc.x += x0.x + x1.x + x2.x + x3.x;
        acc.y += x0.y + x1.y + x2.y + x3.y;
        acc.z += x0.z + x1.z + x2.z + x3.z;
        acc.w += x0.w + x1.w + x2.w + x3.w;
    }
    for (; j < total; j += 4) {
        float4 x = M4[sidx[j] * 64 + f];
        acc.x += x.x; acc.y += x.y; acc.z += x.z; acc.w += x.w;
    }

    red[t] = acc;
    __syncthreads();
    if (g == 0) {
        float4 a = red[f], b = red[f + 64], c = red[f + 128], d = red[f + 192];
        float dv = g_dvis[i];
        float4 bv = *(const float4*)&bias[f * 4];
        float4 o;
        o.x = fmaf(a.x + b.x + c.x + d.x, dv, bv.x);
        o.y = fmaf(a.y + b.y + c.y + d.y, dv, bv.y);
        o.z = fmaf(a.z + b.z + c.z + d.z, dv, bv.z);
        o.w = fmaf(a.w + b.w + c.w + d.w, dv, bv.w);
        *(float4*)&out[i * FF + f * 4] = o;
    }
}

// ============================================================
extern "C" void kernel_launch(void* const* d_in, const int* in_sizes, int n_in,
                              void* d_out, int out_size) {
    const float* X    = (const float*)d_in[0];   // [8192,256]
    const float* H    = (const float*)d_in[1];   // [8192,1024]
    const float* Wm   = (const float*)d_in[2];   // [256,256]
    const float* bias = (const float*)d_in[3];   // [256]
    float* out = (float*)d_out;

    pack_all   <<<NN / 32, 256>>>(H);
    edge_gather<<<EE, 256>>>(X);
    dim3 g(FF / 64, EE / 128);
    gemm_mw    <<<g, 256>>>(Wm);
    node_gather<<<NN, 256>>>(bias, out);
}

// round 6
// speedup vs baseline: 2.3661x; 1.0280x over previous
#include <cuda_runtime.h>

#define NN 8192
#define EE 1024
#define FF 256
#define NW (NN/32)   // 256 words per edge row (transposed bits)
#define EW (EE/32)   // 32 words per node row

// ---- scratch (no allocations allowed; device globals) ----
__device__ float    g_dvis[NN];                     // dv^{-1/2}
__device__ unsigned g_HbT[EE * NW];                 // H^T bitpacked: [edge][node-word]
__device__ unsigned g_HbR[NN * EW];                 // H bitpacked:   [node][edge-word]
__device__ __align__(16) float g_M [EE * FF];       // edge features (De^-1 H^T Dv^-1/2 X)
__device__ __align__(16) float g_MW[EE * FF];       // M @ W^T

// ============================================================
// One-pass pack: coalesced read of H, produces HbR, HbT (via
// in-warp bit transpose) and dv^{-1/2}. CTA = 32 rows x 1024 cols.
// ============================================================
__global__ void __launch_bounds__(256) pack_all(const float* __restrict__ H) {
    const int r0 = blockIdx.x * 32;
    const int w  = threadIdx.x >> 5;
    const int l  = threadIdx.x & 31;

    __shared__ unsigned smask[32][32];   // [col-chunk][row] row-bitmasks

    int cnt[4] = {0, 0, 0, 0};
    for (int ch = 0; ch < 32; ++ch) {
        const int c0 = ch * 32;
        #pragma unroll
        for (int k = 0; k < 4; ++k) {
            const int row = w + 8 * k;
            float v = H[(long)(r0 + row) * EE + c0 + l];   // 128B coalesced
            unsigned m = __ballot_sync(0xffffffffu, v != 0.f);
            cnt[k] += __popc(m);
            if (l == 0) {
                smask[ch][row] = m;
                g_HbR[(r0 + row) * EW + ch] = m;
            }
        }
    }
    if (l == 0) {
        #pragma unroll
        for (int k = 0; k < 4; ++k)
            g_dvis[r0 + w + 8 * k] = rsqrtf((float)cnt[k]);
    }
    __syncthreads();

    const int wordIdx = blockIdx.x;
    #pragma unroll
    for (int q = 0; q < 4; ++q) {
        const int cc = w + 8 * q;
        const unsigned rm = smask[cc][l];
        #pragma unroll
        for (int c = 0; c < 32; ++c) {
            unsigned colm = __ballot_sync(0xffffffffu, (rm >> c) & 1u);
            if (l == 0) g_HbT[(cc * 32 + c) * NW + wordIdx] = colm;
        }
    }
}

// ============================================================
// Pass A: M[e] = (1/de) * sum_{i in e} dvis[i] * X[i]
// one CTA per edge. 4 row-groups x 64 threads, float4, 8-deep MLP.
// ============================================================
#define MAX_DE 1024
__global__ void __launch_bounds__(256) edge_gather(const float* __restrict__ X) {
    const int e = blockIdx.x;
    const int t = threadIdx.x;
    const int lane = t & 31, wid = t >> 5;
    const int f = t & 63;
    const int g = t >> 6;

    __shared__ unsigned short sidx[MAX_DE];
    __shared__ float          sdvv[MAX_DE];
    __shared__ int wtot[8];
    __shared__ int warpOff[9];
    __shared__ float4 red[256];

    unsigned m = g_HbT[e * NW + t];
    int cnt = __popc(m);
    int scan = cnt;
    #pragma unroll
    for (int o = 1; o < 32; o <<= 1) {
        int v = __shfl_up_sync(0xffffffffu, scan, o);
        if (lane >= o) scan += v;
    }
    if (lane == 31) wtot[wid] = scan;
    __syncthreads();
    if (t == 0) {
        int s = 0;
        #pragma unroll
        for (int w = 0; w < 8; ++w) { warpOff[w] = s; s += wtot[w]; }
        warpOff[8] = s;
    }
    __syncthreads();

    int off = warpOff[wid] + (scan - cnt);
    const int base = t * 32;
    while (m) {
        int b = __ffs(m) - 1;
        m &= m - 1;
        int node = base + b;
        sidx[off] = (unsigned short)node;
        sdvv[off] = g_dvis[node];
        ++off;
    }
    __syncthreads();

    const int total = warpOff[8];
    const float4* X4 = (const float4*)X;
    float4 acc = make_float4(0.f, 0.f, 0.f, 0.f);

    int j = g;
    for (; j + 28 < total; j += 32) {
        int   n0 = sidx[j],      n1 = sidx[j + 4],  n2 = sidx[j + 8],  n3 = sidx[j + 12];
        int   n4 = sidx[j + 16], n5 = sidx[j + 20], n6 = sidx[j + 24], n7 = sidx[j + 28];
        float s0 = sdvv[j],      s1 = sdvv[j + 4],  s2 = sdvv[j + 8],  s3 = sdvv[j + 12];
        float s4 = sdvv[j + 16], s5 = sdvv[j + 20], s6 = sdvv[j + 24], s7 = sdvv[j + 28];
        float4 x0 = X4[n0 * 64 + f];
        float4 x1 = X4[n1 * 64 + f];
        float4 x2 = X4[n2 * 64 + f];
        float4 x3 = X4[n3 * 64 + f];
        float4 x4 = X4[n4 * 64 + f];
        float4 x5 = X4[n5 * 64 + f];
        float4 x6 = X4[n6 * 64 + f];
        float4 x7 = X4[n7 * 64 + f];
        acc.x = fmaf(x0.x, s0, acc.x); acc.y = fmaf(x0.y, s0, acc.y);
        acc.z = fmaf(x0.z, s0, acc.z); acc.w = fmaf(x0.w, s0, acc.w);
        acc.x = fmaf(x1.x, s1, acc.x); acc.y = fmaf(x1.y, s1, acc.y);
        acc.z = fmaf(x1.z, s1, acc.z); acc.w = fmaf(x1.w, s1, acc.w);
        acc.x = fmaf(x2.x, s2, acc.x); acc.y = fmaf(x2.y, s2, acc.y);
        acc.z = fmaf(x2.z, s2, acc.z); acc.w = fmaf(x2.w, s2, acc.w);
        acc.x = fmaf(x3.x, s3, acc.x); acc.y = fmaf(x3.y, s3, acc.y);
        acc.z = fmaf(x3.z, s3, acc.z); acc.w = fmaf(x3.w, s3, acc.w);
        acc.x = fmaf(x4.x, s4, acc.x); acc.y = fmaf(x4.y, s4, acc.y);
        acc.z = fmaf(x4.z, s4, acc.z); acc.w = fmaf(x4.w, s4, acc.w);
        acc.x = fmaf(x5.x, s5, acc.x); acc.y = fmaf(x5.y, s5, acc.y);
        acc.z = fmaf(x5.z, s5, acc.z); acc.w = fmaf(x5.w, s5, acc.w);
        acc.x = fmaf(x6.x, s6, acc.x); acc.y = fmaf(x6.y, s6, acc.y);
        acc.z = fmaf(x6.z, s6, acc.z); acc.w = fmaf(x6.w, s6, acc.w);
        acc.x = fmaf(x7.x, s7, acc.x); acc.y = fmaf(x7.y, s7, acc.y);
        acc.z = fmaf(x7.z, s7, acc.z); acc.w = fmaf(x7.w, s7, acc.w);
    }
    for (; j < total; j += 4) {
        int n = sidx[j]; float s = sdvv[j];
        float4 x = X4[n * 64 + f];
        acc.x = fmaf(x.x, s, acc.x); acc.y = fmaf(x.y, s, acc.y);
        acc.z = fmaf(x.z, s, acc.z); acc.w = fmaf(x.w, s, acc.w);
    }

    red[t] = acc;
    __syncthreads();
    if (g == 0) {
        float4 a = red[f], b = red[f + 64], c = red[f + 128], d = red[f + 192];
        float di = 1.f / (float)total;
        float4 o;
        o.x = (a.x + b.x + c.x + d.x) * di;
        o.y = (a.y + b.y + c.y + d.y) * di;
        o.z = (a.z + b.z + c.z + d.z) * di;
        o.w = (a.w + b.w + c.w + d.w) * di;
        *(float4*)&g_M[e * FF + f * 4] = o;
    }
}

// ============================================================
// g_MW = g_M @ W^T   ([1024,256] @ [256,256], both K-major)
// ============================================================
__global__ void __launch_bounds__(256) gemm_mw(const float* __restrict__ Wm) {
    __shared__ float As[32][128];
    __shared__ float Bs[32][64];

    const int tid = threadIdx.x;
    const int ty = tid >> 4;
    const int tx = tid & 15;
    const int i0 = blockIdx.y * 128;
    const int o0 = blockIdx.x * 64;

    float acc[8][4];
    #pragma unroll
    for (int r = 0; r < 8; ++r)
        #pragma unroll
        for (int c = 0; c < 4; ++c) acc[r][c] = 0.f;

    for (int kc = 0; kc < FF; kc += 32) {
        #pragma unroll
        for (int l = 0; l < 4; ++l) {
            int linear = tid + 256 * l;
            int i  = linear >> 3;
            int kq = (linear & 7) << 2;
            float4 v = *(const float4*)&g_M[(i0 + i) * FF + kc + kq];
            As[kq + 0][i] = v.x; As[kq + 1][i] = v.y;
            As[kq + 2][i] = v.z; As[kq + 3][i] = v.w;
        }
        #pragma unroll
        for (int l = 0; l < 2; ++l) {
            int linear = tid + 256 * l;
            int o  = linear >> 3;
            int kq = (linear & 7) << 2;
            float4 v = *(const float4*)&Wm[(o0 + o) * FF + kc + kq];
            Bs[kq + 0][o] = v.x; Bs[kq + 1][o] = v.y;
            Bs[kq + 2][o] = v.z; Bs[kq + 3][o] = v.w;
        }
        __syncthreads();
        #pragma unroll
        for (int kk = 0; kk < 32; ++kk) {
            float4 b4 = *(const float4*)&Bs[kk][tx * 4];
            float4 a0 = *(const float4*)&As[kk][ty * 8];
            float4 a1 = *(const float4*)&As[kk][ty * 8 + 4];
            float a[8] = {a0.x, a0.y, a0.z, a0.w, a1.x, a1.y, a1.z, a1.w};
            float bb[4] = {b4.x, b4.y, b4.z, b4.w};
            #pragma unroll
            for (int r = 0; r < 8; ++r)
                #pragma unroll
                for (int c = 0; c < 4; ++c)
                    acc[r][c] = fmaf(a[r], bb[c], acc[r][c]);
        }
        __syncthreads();
    }

    #pragma unroll
    for (int r = 0; r < 8; ++r) {
        int i = i0 + ty * 8 + r;
        float4 o4;
        o4.x = acc[r][0]; o4.y = acc[r][1];
        o4.z = acc[r][2]; o4.w = acc[r][3];
        *(float4*)&g_MW[i * FF + o0 + tx * 4] = o4;
    }
}

// ============================================================
// Pass B (fused epilogue): out[i] = dvis[i] * sum_{e ni i} MW[e] + b
// TWO nodes per CTA: threads 0-127 -> node 2*bid, 128-255 -> 2*bid+1.
// Per half: 2 row-groups x 64 threads, float4, 8-deep MLP.
// ============================================================
#define MAX_DV 128
__global__ void __launch_bounds__(256) node_gather(const float* __restrict__ bias,
                                                   float* __restrict__ out) {
    const int t    = threadIdx.x;
    const int half = t >> 7;           // 0 or 1
    const int ht   = t & 127;          // id within half
    const int i    = blockIdx.x * 2 + half;
    const int f    = ht & 63;          // float4 column
    const int g    = ht >> 6;          // row group 0/1

    __shared__ unsigned short sidx[2][MAX_DV];
    __shared__ int stot[2];
    __shared__ float4 red[256];

    // decode: warp 0 handles node half=0, warp 4 handles half=1
    if (ht < 32) {
        unsigned m = g_HbR[i * EW + ht];
        int cnt = __popc(m);
        int scan = cnt;
        #pragma unroll
        for (int o = 1; o < 32; o <<= 1) {
            int v = __shfl_up_sync(0xffffffffu, scan, o);
            if (ht >= o) scan += v;
        }
        int off = scan - cnt;
        const int base = ht * 32;
        while (m) {
            int b = __ffs(m) - 1;
            m &= m - 1;
            sidx[half][off++] = (unsigned short)(base + b);
        }
        if (ht == 31) stot[half] = scan;
    }
    __syncthreads();

    const int total = stot[half];
    const unsigned short* idx = sidx[half];
    const float4* M4 = (const float4*)g_MW;
    float4 acc = make_float4(0.f, 0.f, 0.f, 0.f);

    // group g takes rows j = g, g+2, g+4, ...; 8 loads in flight
    int j = g;
    for (; j + 14 < total; j += 16) {
        int e0 = idx[j],      e1 = idx[j + 2],  e2 = idx[j + 4],  e3 = idx[j + 6];
        int e4 = idx[j + 8],  e5 = idx[j + 10], e6 = idx[j + 12], e7 = idx[j + 14];
        float4 x0 = M4[e0 * 64 + f];
        float4 x1 = M4[e1 * 64 + f];
        float4 x2 = M4[e2 * 64 + f];
        float4 x3 = M4[e3 * 64 + f];
        float4 x4 = M4[e4 * 64 + f];
        float4 x5 = M4[e5 * 64 + f];
        float4 x6 = M4[e6 * 64 + f];
        float4 x7 = M4[e7 * 64 + f];
        acc.x += x0.x + x1.x + x2.x + x3.x;
        acc.y += x0.y + x1.y + x2.y + x3.y;
        acc.z += x0.z + x1.z + x2.z + x3.z;
        acc.w += x0.w + x1.w + x2.w + x3.w;
        acc.x += x4.x + x5.x + x6.x + x7.x;
        acc.y += x4.y + x5.y + x6.y + x7.y;
        acc.z += x4.z + x5.z + x6.z + x7.z;
        acc.w += x4.w + x5.w + x6.w + x7.w;
    }
    for (; j < total; j += 2) {
        float4 x = M4[idx[j] * 64 + f];
        acc.x += x.x; acc.y += x.y; acc.z += x.z; acc.w += x.w;
    }

    red[t] = acc;
    __syncthreads();
    if (g == 0) {
        float4 a = red[half * 128 + f];
        float4 b = red[half * 128 + 64 + f];
        float dv = g_dvis[i];
        float4 bv = *(const float4*)&bias[f * 4];
        float4 o;
        o.x = fmaf(a.x + b.x, dv, bv.x);
        o.y = fmaf(a.y + b.y, dv, bv.y);
        o.z = fmaf(a.z + b.z, dv, bv.z);
        o.w = fmaf(a.w + b.w, dv, bv.w);
        *(float4*)&out[i * FF + f * 4] = o;
    }
}

// ============================================================
extern "C" void kernel_launch(void* const* d_in, const int* in_sizes, int n_in,
                              void* d_out, int out_size) {
    const float* X    = (const float*)d_in[0];   // [8192,256]
    const float* H    = (const float*)d_in[1];   // [8192,1024]
    const float* Wm   = (const float*)d_in[2];   // [256,256]
    const float* bias = (const float*)d_in[3];   // [256]
    float* out = (float*)d_out;

    pack_all   <<<NN / 32, 256>>>(H);
    edge_gather<<<EE, 256>>>(X);
    dim3 g1(FF / 64, EE / 128);
    gemm_mw    <<<g1, 256>>>(Wm);
    node_gather<<<NN / 2, 256>>>(bias, out);
}